// round 3
// baseline (speedup 1.0000x reference)
#include <cuda_runtime.h>
#include <cstdint>
#include <cstddef>

#define B_    8
#define CIN_  64
#define COUT_ 64
#define HW_   256
#define MID_  64
#define NP_   4
#define NL_   5
#define CHUNK 4
#define TW    32

// Scratch: per-batch materialized conv weights and biases (no cudaMalloc allowed)
__device__ float g_w[B_ * COUT_ * CIN_ * 9];   // [b][cout][cin][ky][kx]
__device__ float g_b[B_ * COUT_];              // [b][cout]

// ---------------------------------------------------------------------------
// Kernel 1: hypernetwork embed.
// grid = (8 cin-groups, 8 batches), 256 threads.
// w1[b, cin*64+m] = b_wp + b_wi + h[b]@W_wp^T + index@W_wi^T
// w2[b, cin, jj]  = b_we[jj] + sum_m w1[cin,m] * W_we[jj, m]   (jj = cout*9+kk)
// g_w[b, cout, cin, kk] = conv_weight[cout,cin,kk] + w2
// g_b[b, cout] = conv_bias + h@W_bp^T + index@W_bi^T (+zero biases)
// ---------------------------------------------------------------------------
__global__ void embed_kernel(
    const float* __restrict__ h,   const float* __restrict__ index,
    const float* __restrict__ conv_weight, const float* __restrict__ conv_bias,
    const float* __restrict__ W_wp, const float* __restrict__ b_wp,
    const float* __restrict__ W_wi, const float* __restrict__ b_wi,
    const float* __restrict__ W_we, const float* __restrict__ b_we,
    const float* __restrict__ W_bp, const float* __restrict__ b_bp,
    const float* __restrict__ W_bi, const float* __restrict__ b_bi)
{
    const int g = blockIdx.x;       // cin group: cins [g*8, g*8+8)
    const int b = blockIdx.y;
    const int tid = threadIdx.x;

    __shared__ float hs[NP_];
    __shared__ float is_[NL_];
    __shared__ float w1[8 * MID_];  // w1 rows for this cin group

    if (tid < NP_) hs[tid] = h[b * NP_ + tid];
    if (tid < NL_) is_[tid] = index[tid];
    __syncthreads();

    for (int il = tid; il < 8 * MID_; il += blockDim.x) {
        int i = g * 8 * MID_ + il;                  // global row in [0, 4096)
        float v = b_wp[i] + b_wi[i];
        #pragma unroll
        for (int p = 0; p < NP_; p++) v += hs[p] * W_wp[i * NP_ + p];
        #pragma unroll
        for (int l = 0; l < NL_; l++) v += is_[l] * W_wi[i * NL_ + l];
        w1[il] = v;
    }
    __syncthreads();

    for (int e = tid; e < 8 * 576; e += blockDim.x) {
        int cl = e / 576;
        int jj = e - cl * 576;                      // cout*9 + kk
        int cin = g * 8 + cl;
        float s = b_we[jj];
        const float* wr  = &W_we[jj * MID_];
        const float* w1r = &w1[cl * MID_];
        #pragma unroll 8
        for (int m = 0; m < MID_; m++) s += w1r[m] * wr[m];
        int cout = jj / 9;
        int kk   = jj - cout * 9;
        int idx  = (cout * CIN_ + cin) * 9 + kk;
        g_w[b * COUT_ * CIN_ * 9 + idx] = conv_weight[idx] + s;
    }

    if (g == 0 && tid < COUT_) {
        float v = conv_bias[tid] + b_bp[tid] + b_bi[tid];
        #pragma unroll
        for (int p = 0; p < NP_; p++) v += hs[p] * W_bp[tid * NP_ + p];
        #pragma unroll
        for (int l = 0; l < NL_; l++) v += is_[l] * W_bi[tid * NL_ + l];
        g_b[b * COUT_ + tid] = v;
    }
}

// ---------------------------------------------------------------------------
// Packed f32x2 helpers (sm_103a): one fma-pipe op = 2 fp32 FMAs per lane.
// ---------------------------------------------------------------------------
__device__ __forceinline__ uint64_t bcast2(float v) {
    uint64_t r;
    asm("mov.b64 %0, {%1, %1};" : "=l"(r) : "f"(v));
    return r;
}
__device__ __forceinline__ void ffma2(uint64_t& d, uint64_t a, uint64_t b) {
    asm("fma.rn.f32x2 %0, %1, %2, %0;" : "+l"(d) : "l"(a), "l"(b));
}
__device__ __forceinline__ float2 unpack2(uint64_t v) {
    float2 f;
    asm("mov.b64 {%0, %1}, %2;" : "=f"(f.x), "=f"(f.y) : "l"(v));
    return f;
}

// ---------------------------------------------------------------------------
// Kernel 2: per-sample-weights 3x3 conv (stride 1, pad 1).
// grid = (8 x-tiles, 8 y-tiles, B*4 z) ; z = b*4 + cout_group (16 couts each).
// 256 threads: 16x16 layout, each thread computes a 2x2 pixel micro-tile for
// 16 couts packed as 8 f32x2 cout pairs (weight pair via broadcast LDS.64).
// ---------------------------------------------------------------------------
__global__ __launch_bounds__(256, 2)
void conv_kernel(const float* __restrict__ x, float* __restrict__ out)
{
    __shared__ float in_s[CHUNK][34][36];  // halo tile, +2 col pad vs 34 for banks
    __shared__ float w_s[CHUNK][9][16];    // [cin][k][cout] -> cout contiguous

    const int tid = threadIdx.x;
    const int tx = tid & 15;
    const int ty = tid >> 4;
    const int x0 = blockIdx.x * TW;
    const int y0 = blockIdx.y * TW;
    const int zb = blockIdx.z;
    const int b = zb >> 2;
    const int cout0 = (zb & 3) * 16;

    const float* xb = x + ((size_t)(b * CIN_) << 16);

    uint64_t acc[8][4];                    // [cout-pair][dy*2+dx]
    #pragma unroll
    for (int cp = 0; cp < 8; cp++)
        #pragma unroll
        for (int q = 0; q < 4; q++) acc[cp][q] = 0ull;

    const int lx = tx * 2;
    const int ly = ty * 2;

    for (int ch = 0; ch < CIN_ / CHUNK; ch++) {
        __syncthreads();
        // stage input halo tiles for CHUNK cins
        for (int e = tid; e < CHUNK * 34 * 34; e += 256) {
            int ci  = e / 1156;
            int rem = e - ci * 1156;
            int r   = rem / 34;
            int c   = rem - r * 34;
            int gy = y0 - 1 + r;
            int gx = x0 - 1 + c;
            float v = 0.f;
            if ((unsigned)gy < 256u && (unsigned)gx < 256u)
                v = xb[((ch * CHUNK + ci) << 16) | (gy << 8) | gx];
            in_s[ci][r][c] = v;
        }
        // stage weights for CHUNK cins x 16 couts x 9 taps
        for (int e = tid; e < CHUNK * 9 * 16; e += 256) {
            int co = e & 15;
            int t  = e >> 4;
            int ci = t / 9;
            int k  = t - ci * 9;
            w_s[ci][k][co] =
                g_w[((b * COUT_ + cout0 + co) * CIN_ + ch * CHUNK + ci) * 9 + k];
        }
        __syncthreads();

        #pragma unroll
        for (int ci = 0; ci < CHUNK; ci++) {
            #pragma unroll
            for (int ky = 0; ky < 3; ky++) {
                uint64_t ip0[4], ip1[4];
                #pragma unroll
                for (int j = 0; j < 4; j++) {
                    ip0[j] = bcast2(in_s[ci][ly + ky][lx + j]);
                    ip1[j] = bcast2(in_s[ci][ly + ky + 1][lx + j]);
                }
                #pragma unroll
                for (int kx = 0; kx < 3; kx++) {
                    #pragma unroll
                    for (int cp = 0; cp < 8; cp++) {
                        uint64_t w2 =
                            *(const uint64_t*)&w_s[ci][ky * 3 + kx][cp * 2];
                        ffma2(acc[cp][0], ip0[kx + 0], w2);
                        ffma2(acc[cp][1], ip0[kx + 1], w2);
                        ffma2(acc[cp][2], ip1[kx + 0], w2);
                        ffma2(acc[cp][3], ip1[kx + 1], w2);
                    }
                }
            }
        }
    }

    // epilogue: add bias, repack so stores are (px, px+1) contiguous float2
    #pragma unroll
    for (int cp = 0; cp < 8; cp++) {
        int c0 = cout0 + cp * 2;
        float b0 = g_b[b * COUT_ + c0];
        float b1 = g_b[b * COUT_ + c0 + 1];
        #pragma unroll
        for (int dy = 0; dy < 2; dy++) {
            float2 pa = unpack2(acc[cp][dy * 2 + 0]);  // (c0, px), (c0+1, px)
            float2 pb = unpack2(acc[cp][dy * 2 + 1]);  // (c0, px+1), (c0+1, px+1)
            int py = y0 + ly + dy;
            int px = x0 + lx;
            float2 o0 = make_float2(pa.x + b0, pb.x + b0);
            float2 o1 = make_float2(pa.y + b1, pb.y + b1);
            *(float2*)&out[(((size_t)(b * COUT_ + c0)) << 16) + (py << 8) + px] = o0;
            *(float2*)&out[(((size_t)(b * COUT_ + c0 + 1)) << 16) + (py << 8) + px] = o1;
        }
    }
}

// ---------------------------------------------------------------------------
// kernel_launch — inputs in metadata order:
// x, h, index, conv_weight, conv_bias, W_wp, b_wp, W_wi, b_wi, W_we, b_we,
// W_bp, b_bp, W_bi, b_bi
// ---------------------------------------------------------------------------
extern "C" void kernel_launch(void* const* d_in, const int* in_sizes, int n_in,
                              void* d_out, int out_size)
{
    const float* x           = (const float*)d_in[0];
    const float* h           = (const float*)d_in[1];
    const float* index       = (const float*)d_in[2];
    const float* conv_weight = (const float*)d_in[3];
    const float* conv_bias   = (const float*)d_in[4];
    const float* W_wp        = (const float*)d_in[5];
    const float* b_wp        = (const float*)d_in[6];
    const float* W_wi        = (const float*)d_in[7];
    const float* b_wi        = (const float*)d_in[8];
    const float* W_we        = (const float*)d_in[9];
    const float* b_we        = (const float*)d_in[10];
    const float* W_bp        = (const float*)d_in[11];
    const float* b_bp        = (const float*)d_in[12];
    const float* W_bi        = (const float*)d_in[13];
    const float* b_bi        = (const float*)d_in[14];
    float* out = (float*)d_out;

    dim3 g1(8, 8);
    embed_kernel<<<g1, 256>>>(h, index, conv_weight, conv_bias,
                              W_wp, b_wp, W_wi, b_wi, W_we, b_we,
                              W_bp, b_bp, W_bi, b_bi);

    dim3 g2(8, 8, B_ * 4);
    conv_kernel<<<g2, 256>>>(x, out);
}

// round 4
// speedup vs baseline: 1.0004x; 1.0004x over previous
#include <cuda_runtime.h>
#include <cstdint>
#include <cstddef>

#define B_    8
#define CIN_  64
#define COUT_ 64
#define HW_   256
#define MID_  64
#define NP_   4
#define NL_   5
#define CHUNK 4
#define TW    32

// Scratch: per-batch materialized conv weights and biases (no cudaMalloc allowed)
__device__ float g_w[B_ * COUT_ * CIN_ * 9];   // [b][cout][cin][ky][kx]
__device__ float g_b[B_ * COUT_];              // [b][cout]

// ---------------------------------------------------------------------------
// Kernel 1: hypernetwork embed.
// grid = (8 cin-groups, 8 batches), 256 threads.
// w1[b, cin*64+m] = b_wp + b_wi + h[b]@W_wp^T + index@W_wi^T
// w2[b, cin, jj]  = b_we[jj] + sum_m w1[cin,m] * W_we[jj, m]   (jj = cout*9+kk)
// g_w[b, cout, cin, kk] = conv_weight[cout,cin,kk] + w2
// g_b[b, cout] = conv_bias + h@W_bp^T + index@W_bi^T (+zero biases)
// ---------------------------------------------------------------------------
__global__ void embed_kernel(
    const float* __restrict__ h,   const float* __restrict__ index,
    const float* __restrict__ conv_weight, const float* __restrict__ conv_bias,
    const float* __restrict__ W_wp, const float* __restrict__ b_wp,
    const float* __restrict__ W_wi, const float* __restrict__ b_wi,
    const float* __restrict__ W_we, const float* __restrict__ b_we,
    const float* __restrict__ W_bp, const float* __restrict__ b_bp,
    const float* __restrict__ W_bi, const float* __restrict__ b_bi)
{
    const int g = blockIdx.x;       // cin group: cins [g*8, g*8+8)
    const int b = blockIdx.y;
    const int tid = threadIdx.x;

    __shared__ float hs[NP_];
    __shared__ float is_[NL_];
    __shared__ float w1[8 * MID_];  // w1 rows for this cin group

    if (tid < NP_) hs[tid] = h[b * NP_ + tid];
    if (tid < NL_) is_[tid] = index[tid];
    __syncthreads();

    for (int il = tid; il < 8 * MID_; il += blockDim.x) {
        int i = g * 8 * MID_ + il;                  // global row in [0, 4096)
        float v = b_wp[i] + b_wi[i];
        #pragma unroll
        for (int p = 0; p < NP_; p++) v += hs[p] * W_wp[i * NP_ + p];
        #pragma unroll
        for (int l = 0; l < NL_; l++) v += is_[l] * W_wi[i * NL_ + l];
        w1[il] = v;
    }
    __syncthreads();

    for (int e = tid; e < 8 * 576; e += blockDim.x) {
        int cl = e / 576;
        int jj = e - cl * 576;                      // cout*9 + kk
        int cin = g * 8 + cl;
        float s = b_we[jj];
        const float* wr  = &W_we[jj * MID_];
        const float* w1r = &w1[cl * MID_];
        #pragma unroll 8
        for (int m = 0; m < MID_; m++) s += w1r[m] * wr[m];
        int cout = jj / 9;
        int kk   = jj - cout * 9;
        int idx  = (cout * CIN_ + cin) * 9 + kk;
        g_w[b * COUT_ * CIN_ * 9 + idx] = conv_weight[idx] + s;
    }

    if (g == 0 && tid < COUT_) {
        float v = conv_bias[tid] + b_bp[tid] + b_bi[tid];
        #pragma unroll
        for (int p = 0; p < NP_; p++) v += hs[p] * W_bp[tid * NP_ + p];
        #pragma unroll
        for (int l = 0; l < NL_; l++) v += is_[l] * W_bi[tid * NL_ + l];
        g_b[b * COUT_ + tid] = v;
    }
}

// ---------------------------------------------------------------------------
// Packed f32x2 helpers (sm_103a): one fma-pipe op = 2 fp32 FMAs per lane.
// ---------------------------------------------------------------------------
__device__ __forceinline__ uint64_t bcast2(float v) {
    uint64_t r;
    asm("mov.b64 %0, {%1, %1};" : "=l"(r) : "f"(v));
    return r;
}
__device__ __forceinline__ void ffma2(uint64_t& d, uint64_t a, uint64_t b) {
    asm("fma.rn.f32x2 %0, %1, %2, %0;" : "+l"(d) : "l"(a), "l"(b));
}
__device__ __forceinline__ float2 unpack2(uint64_t v) {
    float2 f;
    asm("mov.b64 {%0, %1}, %2;" : "=f"(f.x), "=f"(f.y) : "l"(v));
    return f;
}

// ---------------------------------------------------------------------------
// Kernel 2: per-sample-weights 3x3 conv (stride 1, pad 1).
// grid = (8 x-tiles, 8 y-tiles, B*4 z) ; z = b*4 + cout_group (16 couts each).
// 256 threads: 16x16 layout, each thread computes a 2x2 pixel micro-tile for
// 16 couts packed as 8 f32x2 cout pairs (weight pair via broadcast LDS.64).
// ---------------------------------------------------------------------------
__global__ __launch_bounds__(256, 2)
void conv_kernel(const float* __restrict__ x, float* __restrict__ out)
{
    __shared__ float in_s[CHUNK][34][36];  // halo tile, +2 col pad vs 34 for banks
    __shared__ float w_s[CHUNK][9][16];    // [cin][k][cout] -> cout contiguous

    const int tid = threadIdx.x;
    const int tx = tid & 15;
    const int ty = tid >> 4;
    const int x0 = blockIdx.x * TW;
    const int y0 = blockIdx.y * TW;
    const int zb = blockIdx.z;
    const int b = zb >> 2;
    const int cout0 = (zb & 3) * 16;

    const float* xb = x + ((size_t)(b * CIN_) << 16);

    uint64_t acc[8][4];                    // [cout-pair][dy*2+dx]
    #pragma unroll
    for (int cp = 0; cp < 8; cp++)
        #pragma unroll
        for (int q = 0; q < 4; q++) acc[cp][q] = 0ull;

    const int lx = tx * 2;
    const int ly = ty * 2;

    for (int ch = 0; ch < CIN_ / CHUNK; ch++) {
        __syncthreads();
        // stage input halo tiles for CHUNK cins
        for (int e = tid; e < CHUNK * 34 * 34; e += 256) {
            int ci  = e / 1156;
            int rem = e - ci * 1156;
            int r   = rem / 34;
            int c   = rem - r * 34;
            int gy = y0 - 1 + r;
            int gx = x0 - 1 + c;
            float v = 0.f;
            if ((unsigned)gy < 256u && (unsigned)gx < 256u)
                v = xb[((ch * CHUNK + ci) << 16) | (gy << 8) | gx];
            in_s[ci][r][c] = v;
        }
        // stage weights for CHUNK cins x 16 couts x 9 taps
        for (int e = tid; e < CHUNK * 9 * 16; e += 256) {
            int co = e & 15;
            int t  = e >> 4;
            int ci = t / 9;
            int k  = t - ci * 9;
            w_s[ci][k][co] =
                g_w[((b * COUT_ + cout0 + co) * CIN_ + ch * CHUNK + ci) * 9 + k];
        }
        __syncthreads();

        #pragma unroll
        for (int ci = 0; ci < CHUNK; ci++) {
            #pragma unroll
            for (int ky = 0; ky < 3; ky++) {
                uint64_t ip0[4], ip1[4];
                #pragma unroll
                for (int j = 0; j < 4; j++) {
                    ip0[j] = bcast2(in_s[ci][ly + ky][lx + j]);
                    ip1[j] = bcast2(in_s[ci][ly + ky + 1][lx + j]);
                }
                #pragma unroll
                for (int kx = 0; kx < 3; kx++) {
                    #pragma unroll
                    for (int cp = 0; cp < 8; cp++) {
                        uint64_t w2 =
                            *(const uint64_t*)&w_s[ci][ky * 3 + kx][cp * 2];
                        ffma2(acc[cp][0], ip0[kx + 0], w2);
                        ffma2(acc[cp][1], ip0[kx + 1], w2);
                        ffma2(acc[cp][2], ip1[kx + 0], w2);
                        ffma2(acc[cp][3], ip1[kx + 1], w2);
                    }
                }
            }
        }
    }

    // epilogue: add bias, repack so stores are (px, px+1) contiguous float2
    #pragma unroll
    for (int cp = 0; cp < 8; cp++) {
        int c0 = cout0 + cp * 2;
        float b0 = g_b[b * COUT_ + c0];
        float b1 = g_b[b * COUT_ + c0 + 1];
        #pragma unroll
        for (int dy = 0; dy < 2; dy++) {
            float2 pa = unpack2(acc[cp][dy * 2 + 0]);  // (c0, px), (c0+1, px)
            float2 pb = unpack2(acc[cp][dy * 2 + 1]);  // (c0, px+1), (c0+1, px+1)
            int py = y0 + ly + dy;
            int px = x0 + lx;
            float2 o0 = make_float2(pa.x + b0, pb.x + b0);
            float2 o1 = make_float2(pa.y + b1, pb.y + b1);
            *(float2*)&out[(((size_t)(b * COUT_ + c0)) << 16) + (py << 8) + px] = o0;
            *(float2*)&out[(((size_t)(b * COUT_ + c0 + 1)) << 16) + (py << 8) + px] = o1;
        }
    }
}

// ---------------------------------------------------------------------------
// kernel_launch — inputs in metadata order:
// x, h, index, conv_weight, conv_bias, W_wp, b_wp, W_wi, b_wi, W_we, b_we,
// W_bp, b_bp, W_bi, b_bi
// ---------------------------------------------------------------------------
extern "C" void kernel_launch(void* const* d_in, const int* in_sizes, int n_in,
                              void* d_out, int out_size)
{
    const float* x           = (const float*)d_in[0];
    const float* h           = (const float*)d_in[1];
    const float* index       = (const float*)d_in[2];
    const float* conv_weight = (const float*)d_in[3];
    const float* conv_bias   = (const float*)d_in[4];
    const float* W_wp        = (const float*)d_in[5];
    const float* b_wp        = (const float*)d_in[6];
    const float* W_wi        = (const float*)d_in[7];
    const float* b_wi        = (const float*)d_in[8];
    const float* W_we        = (const float*)d_in[9];
    const float* b_we        = (const float*)d_in[10];
    const float* W_bp        = (const float*)d_in[11];
    const float* b_bp        = (const float*)d_in[12];
    const float* W_bi        = (const float*)d_in[13];
    const float* b_bi        = (const float*)d_in[14];
    float* out = (float*)d_out;

    dim3 g1(8, 8);
    embed_kernel<<<g1, 256>>>(h, index, conv_weight, conv_bias,
                              W_wp, b_wp, W_wi, b_wi, W_we, b_we,
                              W_bp, b_bp, W_bi, b_bi);

    dim3 g2(8, 8, B_ * 4);
    conv_kernel<<<g2, 256>>>(x, out);
}

// round 6
// speedup vs baseline: 1.5110x; 1.5103x over previous
#include <cuda_runtime.h>
#include <cuda_fp16.h>
#include <cstdint>
#include <cstddef>

#define B_    8
#define CIN_  64
#define COUT_ 64
#define MID_  64
#define NP_   4
#define NL_   5

// ---------------- scratch (no cudaMalloc allowed) --------------------------
// fp16 hi/lo weight planes: [b][tap(9)][half(hi,lo)][cout(64)][cin(64)]
__device__ uint4 g_whl4[B_ * 9 * 2 * 64 * 8];   // 16B chunks, 1.125 MB
__device__ float g_b[B_ * COUT_];

// ---------------------------------------------------------------------------
// Kernel 1: hypernetwork embed -> fp16 hi/lo weight planes + bias
// ---------------------------------------------------------------------------
__global__ void embed_kernel(
    const float* __restrict__ h,   const float* __restrict__ index,
    const float* __restrict__ conv_weight, const float* __restrict__ conv_bias,
    const float* __restrict__ W_wp, const float* __restrict__ b_wp,
    const float* __restrict__ W_wi, const float* __restrict__ b_wi,
    const float* __restrict__ W_we, const float* __restrict__ b_we,
    const float* __restrict__ W_bp, const float* __restrict__ b_bp,
    const float* __restrict__ W_bi, const float* __restrict__ b_bi)
{
    const int g = blockIdx.x;       // cin group: cins [g*8, g*8+8)
    const int b = blockIdx.y;
    const int tid = threadIdx.x;

    __shared__ float hs[NP_];
    __shared__ float is_[NL_];
    __shared__ float w1[8 * MID_];

    if (tid < NP_) hs[tid] = h[b * NP_ + tid];
    if (tid < NL_) is_[tid] = index[tid];
    __syncthreads();

    for (int il = tid; il < 8 * MID_; il += blockDim.x) {
        int i = g * 8 * MID_ + il;
        float v = b_wp[i] + b_wi[i];
        #pragma unroll
        for (int p = 0; p < NP_; p++) v += hs[p] * W_wp[i * NP_ + p];
        #pragma unroll
        for (int l = 0; l < NL_; l++) v += is_[l] * W_wi[i * NL_ + l];
        w1[il] = v;
    }
    __syncthreads();

    unsigned short* gw = (unsigned short*)g_whl4;

    for (int e = tid; e < 8 * 576; e += blockDim.x) {
        int cl = e / 576;
        int jj = e - cl * 576;                      // cout*9 + kk
        int cin = g * 8 + cl;
        float s = b_we[jj];
        const float* wr  = &W_we[jj * MID_];
        const float* w1r = &w1[cl * MID_];
        #pragma unroll 8
        for (int m = 0; m < MID_; m++) s += w1r[m] * wr[m];
        int cout = jj / 9;
        int kk   = jj - cout * 9;                   // ky*3 + kx
        float wv = conv_weight[(cout * CIN_ + cin) * 9 + kk] + s;

        __half hi = __float2half_rn(wv);
        __half lo = __float2half_rn(wv - __half2float(hi));

        size_t o = (((size_t)(b * 9 + kk) * 2) * 64 + cout) * 64 + cin;
        gw[o]        = __half_as_ushort(hi);        // hh=0 plane
        gw[o + 4096] = __half_as_ushort(lo);        // hh=1 plane (+64*64)
    }

    if (g == 0 && tid < COUT_) {
        float v = conv_bias[tid] + b_bp[tid] + b_bi[tid];
        #pragma unroll
        for (int p = 0; p < NP_; p++) v += hs[p] * W_bp[tid * NP_ + p];
        #pragma unroll
        for (int l = 0; l < NL_; l++) v += is_[l] * W_bi[tid * NL_ + l];
        g_b[b * COUT_ + tid] = v;
    }
}

// ---------------------------------------------------------------------------
// mma.sync / ldmatrix helpers (sm_80 base-target ISA)
// ---------------------------------------------------------------------------
__device__ __forceinline__ uint32_t smem_u32(const void* p) {
    uint32_t a;
    asm("{ .reg .u64 t; cvta.to.shared.u64 t, %1; cvt.u32.u64 %0, t; }"
        : "=r"(a) : "l"(p));
    return a;
}
__device__ __forceinline__ void mma16816(float* c, const uint32_t* a,
                                         const uint32_t* b) {
    asm volatile(
        "mma.sync.aligned.m16n8k16.row.col.f32.f16.f16.f32 "
        "{%0,%1,%2,%3}, {%4,%5,%6,%7}, {%8,%9}, {%0,%1,%2,%3};"
        : "+f"(c[0]), "+f"(c[1]), "+f"(c[2]), "+f"(c[3])
        : "r"(a[0]), "r"(a[1]), "r"(a[2]), "r"(a[3]), "r"(b[0]), "r"(b[1]));
}
__device__ __forceinline__ void ldsm4(uint32_t* r, uint32_t addr) {
    asm volatile("ldmatrix.sync.aligned.m8n8.x4.shared.b16 {%0,%1,%2,%3}, [%4];"
        : "=r"(r[0]), "=r"(r[1]), "=r"(r[2]), "=r"(r[3]) : "r"(addr));
}
__device__ __forceinline__ void ldsm2(uint32_t* r, uint32_t addr) {
    asm volatile("ldmatrix.sync.aligned.m8n8.x2.shared.b16 {%0,%1}, [%2];"
        : "=r"(r[0]), "=r"(r[1]) : "r"(addr));
}

// ---------------------------------------------------------------------------
// Kernel 2: mma.sync conv. grid=(2,256,8) = (half-row, image row y, batch b).
// Smem: A planes [ky 3][hi/lo][row 130][144B] (row=px, 64 fp16 cin + pad);
//       B 2-slot cp.async ring, per tap [hi/lo][cout 64][144B].
// Tap (ky,kx): A fragment rows shifted by kx (no im2col).
// ---------------------------------------------------------------------------
#define A_RS     144
#define A_PLANE  (130 * A_RS)          // 18720
#define A_TOTAL  (6 * A_PLANE)         // 112320
#define B_HALF   (64 * A_RS)           // 9216
#define B_SLOT   (2 * B_HALF)          // 18432
#define B_OFF    A_TOTAL
#define BIAS_OFF (A_TOTAL + 2 * B_SLOT)  // 149184
#define SMEM_DYN (BIAS_OFF + 256)

__global__ __launch_bounds__(256, 1)
void conv_mma_kernel(const float* __restrict__ x, float* __restrict__ out)
{
    extern __shared__ unsigned char sm[];
    const uint32_t sb = smem_u32(sm);
    const int tid = threadIdx.x;
    const int w   = tid >> 5;
    const int l   = tid & 31;
    const int px0 = blockIdx.x * 128;
    const int y   = blockIdx.y;
    const int b   = blockIdx.z;

    float* bias_s = (float*)(sm + BIAS_OFF);
    if (tid < 64) bias_s[tid] = g_b[b * COUT_ + tid];

    // ---- stage A: 3 ky planes x (hi,lo); rows 0..129 = px0-1 .. px0+128 ---
    const float* xb = x + ((size_t)(b * CIN_) << 16);
    for (int u = tid; u < 12480; u += 256) {
        int ky  = u / 4160;
        int rem = u - ky * 4160;
        int cp  = rem / 130;          // cin pair
        int pr  = rem - cp * 130;     // plane row (pixel)
        int gy  = y + ky - 1;
        int gx  = px0 - 1 + pr;
        float v0 = 0.f, v1 = 0.f;
        if ((unsigned)gy < 256u && (unsigned)gx < 256u) {
            const float* p = xb + ((size_t)(cp * 2) << 16) + (gy << 8) + gx;
            v0 = p[0];
            v1 = p[(size_t)1 << 16];
        }
        __half h0 = __float2half_rn(v0), h1 = __float2half_rn(v1);
        __half q0 = __float2half_rn(v0 - __half2float(h0));
        __half q1 = __float2half_rn(v1 - __half2float(h1));
        unsigned off = (unsigned)(pr * A_RS + cp * 4);
        *(__half2*)(sm + (ky * 2 + 0) * A_PLANE + off) = __halves2half2(h0, h1);
        *(__half2*)(sm + (ky * 2 + 1) * A_PLANE + off) = __halves2half2(q0, q1);
    }

    // ---- B cp.async issue helper: tap t -> slot (16KB packed -> padded) ---
    auto issueB = [&](int t, int slot) {
        const char* src = (const char*)g_whl4 + (size_t)(b * 9 + t) * 16384;
        uint32_t dst0 = sb + B_OFF + slot * B_SLOT;
        #pragma unroll
        for (int i = 0; i < 4; i++) {
            int idx = tid + i * 256;
            int hh  = idx >> 9;
            int row = (idx >> 3) & 63;
            int ch  = idx & 7;
            uint32_t d = dst0 + hh * B_HALF + row * A_RS + ch * 16;
            const char* s = src + (((hh * 64 + row) * 8 + ch) << 4);
            asm volatile("cp.async.cg.shared.global [%0], [%1], 16;"
                         :: "r"(d), "l"(s));
        }
    };

    issueB(0, 0);
    asm volatile("cp.async.commit_group;" ::: "memory");

    // per-lane ldmatrix offsets
    const uint32_t a_off = (uint32_t)((l & 15) * A_RS + (l >> 4) * 16);
    const uint32_t b_off = (uint32_t)((l & 7) * A_RS + ((l >> 3) & 1) * 16);

    float c[8][4];
    #pragma unroll
    for (int nt = 0; nt < 8; nt++)
        #pragma unroll
        for (int q = 0; q < 4; q++) c[nt][q] = 0.f;

    #pragma unroll 1
    for (int t = 0; t < 9; t++) {
        if (t < 8) issueB(t + 1, (t + 1) & 1);
        asm volatile("cp.async.commit_group;" ::: "memory");   // empty @ t=8
        asm volatile("cp.async.wait_group 1;" ::: "memory");
        __syncthreads();   // B(t) + (t==0: A staging) visible to all warps

        const int ky = t / 3, kx = t - ky * 3;
        const uint32_t ahi = sb + (ky * 2) * A_PLANE + (w * 16 + kx) * A_RS + a_off;
        const uint32_t alo = ahi + A_PLANE;
        const uint32_t bhi = sb + B_OFF + (t & 1) * B_SLOT + b_off;
        const uint32_t blo = bhi + B_HALF;

        #pragma unroll
        for (int kc = 0; kc < 4; kc++) {
            uint32_t ah[4], al[4];
            ldsm4(ah, ahi + kc * 32);
            ldsm4(al, alo + kc * 32);
            #pragma unroll
            for (int nt = 0; nt < 8; nt++) {
                uint32_t bh[2], bl[2];
                ldsm2(bh, bhi + nt * 8 * A_RS + kc * 32);
                ldsm2(bl, blo + nt * 8 * A_RS + kc * 32);
                mma16816(c[nt], ah, bh);   // hi*hi
                mma16816(c[nt], ah, bl);   // hi*lo
                mma16816(c[nt], al, bh);   // lo*hi
            }
        }
        __syncthreads();   // all reads of slot done before it is re-filled
    }

    // ---- epilogue: C[m=px][n=cout] + bias -> out[b][n][y][px] -------------
    const int gg  = l >> 2, tig = l & 3;
    const int pxb = px0 + w * 16 + gg;
    float* ob = out + (((size_t)b * COUT_) << 16) + (y << 8);
    #pragma unroll
    for (int nt = 0; nt < 8; nt++) {
        int n0 = nt * 8 + tig * 2;
        float bi0 = bias_s[n0], bi1 = bias_s[n0 + 1];
        ob[((size_t)n0 << 16) + pxb]           = c[nt][0] + bi0;
        ob[((size_t)(n0 + 1) << 16) + pxb]     = c[nt][1] + bi1;
        ob[((size_t)n0 << 16) + pxb + 8]       = c[nt][2] + bi0;
        ob[((size_t)(n0 + 1) << 16) + pxb + 8] = c[nt][3] + bi1;
    }
}

// ---------------------------------------------------------------------------
extern "C" void kernel_launch(void* const* d_in, const int* in_sizes, int n_in,
                              void* d_out, int out_size)
{
    const float* x           = (const float*)d_in[0];
    const float* h           = (const float*)d_in[1];
    const float* index       = (const float*)d_in[2];
    const float* conv_weight = (const float*)d_in[3];
    const float* conv_bias   = (const float*)d_in[4];
    const float* W_wp        = (const float*)d_in[5];
    const float* b_wp        = (const float*)d_in[6];
    const float* W_wi        = (const float*)d_in[7];
    const float* b_wi        = (const float*)d_in[8];
    const float* W_we        = (const float*)d_in[9];
    const float* b_we        = (const float*)d_in[10];
    const float* W_bp        = (const float*)d_in[11];
    const float* b_bp        = (const float*)d_in[12];
    const float* W_bi        = (const float*)d_in[13];
    const float* b_bi        = (const float*)d_in[14];
    float* out = (float*)d_out;

    cudaFuncSetAttribute(conv_mma_kernel,
                         cudaFuncAttributeMaxDynamicSharedMemorySize, SMEM_DYN);

    dim3 g1(8, 8);
    embed_kernel<<<g1, 256>>>(h, index, conv_weight, conv_bias,
                              W_wp, b_wp, W_wi, b_wi, W_we, b_we,
                              W_bp, b_bp, W_bi, b_bi);

    dim3 g2(2, 256, B_);
    conv_mma_kernel<<<g2, 256, SMEM_DYN>>>(x, out);
}

// round 9
// speedup vs baseline: 2.8870x; 1.9107x over previous
#include <cuda_runtime.h>
#include <cuda_fp16.h>
#include <cstdint>
#include <cstddef>

#define B_    8
#define CIN_  64
#define COUT_ 64
#define MID_  64
#define NP_   4
#define NL_   5

// ---------------- scratch (no cudaMalloc allowed) --------------------------
// fp16 hi/lo weight planes: [b][tap(9)][half(hi,lo)][cout(64)][cin(64)]
__device__ uint4 g_whl4[B_ * 9 * 2 * 64 * 8];   // 1.125 MB
__device__ float g_b[B_ * COUT_];

// ---------------------------------------------------------------------------
// Kernel 1: hypernetwork embed -> fp16 hi/lo weight planes + bias.
// W_we is smem-tiled (4 tiles of 144 rows x 64, pad 65) so all global reads
// are coalesced and dot products run from smem.
// ---------------------------------------------------------------------------
__global__ __launch_bounds__(256)
void embed_kernel(
    const float* __restrict__ h,   const float* __restrict__ index,
    const float* __restrict__ conv_weight, const float* __restrict__ conv_bias,
    const float* __restrict__ W_wp, const float* __restrict__ b_wp,
    const float* __restrict__ W_wi, const float* __restrict__ b_wi,
    const float* __restrict__ W_we, const float* __restrict__ b_we,
    const float* __restrict__ W_bp, const float* __restrict__ b_bp,
    const float* __restrict__ W_bi, const float* __restrict__ b_bi)
{
    const int g = blockIdx.x;       // cin group: cins [g*8, g*8+8)
    const int b = blockIdx.y;
    const int tid = threadIdx.x;

    __shared__ float hs[NP_];
    __shared__ float is_[NL_];
    __shared__ float w1[8 * MID_];
    __shared__ float Wt[144 * 65];   // padded tile of W_we

    if (tid < NP_) hs[tid] = h[b * NP_ + tid];
    if (tid < NL_) is_[tid] = index[tid];
    __syncthreads();

    for (int il = tid; il < 8 * MID_; il += 256) {
        int i = g * 8 * MID_ + il;
        float v = b_wp[i] + b_wi[i];
        #pragma unroll
        for (int p = 0; p < NP_; p++) v += hs[p] * W_wp[i * NP_ + p];
        #pragma unroll
        for (int l = 0; l < NL_; l++) v += is_[l] * W_wi[i * NL_ + l];
        w1[il] = v;
    }

    unsigned short* gw = (unsigned short*)g_whl4;

    for (int jt = 0; jt < 4; jt++) {
        __syncthreads();
        // coalesced tile load: rows jt*144 .. jt*144+143 of W_we[576][64]
        for (int idx = tid; idx < 144 * 64; idx += 256) {
            int r = idx >> 6, m = idx & 63;
            Wt[r * 65 + m] = W_we[(jt * 144 + r) * 64 + m];
        }
        __syncthreads();

        for (int e = tid; e < 8 * 144; e += 256) {
            int cl  = e / 144;
            int jjl = e - cl * 144;
            int jj  = jt * 144 + jjl;                 // cout*9 + kk
            int cin = g * 8 + cl;
            float s = b_we[jj];
            const float* wr  = &Wt[jjl * 65];
            const float* w1r = &w1[cl * MID_];
            #pragma unroll 16
            for (int m = 0; m < MID_; m++) s += w1r[m] * wr[m];
            int cout = jj / 9;
            int kk   = jj - cout * 9;                 // ky*3 + kx
            float wv = conv_weight[(cout * CIN_ + cin) * 9 + kk] + s;

            __half hi = __float2half_rn(wv);
            __half lo = __float2half_rn(wv - __half2float(hi));
            size_t o = (((size_t)(b * 9 + kk) * 2) * 64 + cout) * 64 + cin;
            gw[o]        = __half_as_ushort(hi);
            gw[o + 4096] = __half_as_ushort(lo);
        }
    }

    if (g == 0 && tid < COUT_) {
        float v = conv_bias[tid] + b_bp[tid] + b_bi[tid];
        #pragma unroll
        for (int p = 0; p < NP_; p++) v += hs[p] * W_bp[tid * NP_ + p];
        #pragma unroll
        for (int l = 0; l < NL_; l++) v += is_[l] * W_bi[tid * NL_ + l];
        g_b[b * COUT_ + tid] = v;
    }
}

// ---------------------------------------------------------------------------
// mma.sync / ldmatrix helpers (base-target ISA)
// ---------------------------------------------------------------------------
__device__ __forceinline__ uint32_t smem_u32(const void* p) {
    uint32_t a;
    asm("{ .reg .u64 t; cvta.to.shared.u64 t, %1; cvt.u32.u64 %0, t; }"
        : "=r"(a) : "l"(p));
    return a;
}
__device__ __forceinline__ void mma16816(float* c, const uint32_t* a,
                                         const uint32_t* b) {
    asm volatile(
        "mma.sync.aligned.m16n8k16.row.col.f32.f16.f16.f32 "
        "{%0,%1,%2,%3}, {%4,%5,%6,%7}, {%8,%9}, {%0,%1,%2,%3};"
        : "+f"(c[0]), "+f"(c[1]), "+f"(c[2]), "+f"(c[3])
        : "r"(a[0]), "r"(a[1]), "r"(a[2]), "r"(a[3]), "r"(b[0]), "r"(b[1]));
}
__device__ __forceinline__ void ldsm4(uint32_t* r, uint32_t addr) {
    asm volatile("ldmatrix.sync.aligned.m8n8.x4.shared.b16 {%0,%1,%2,%3}, [%4];"
        : "=r"(r[0]), "=r"(r[1]), "=r"(r[2]), "=r"(r[3]) : "r"(addr));
}

// ---------------------------------------------------------------------------
// Kernel 2: mma.sync conv. grid=(2,256,8) = (half-row, image row y, batch b).
// A: fp16 (hi only) planes [ky 3][row 130][144B]; weight stays hi/lo split.
// B: 2-slot cp.async ring, per tap [hi/lo][cout 64][144B].
// Tap (ky,kx): A fragment rows shifted by kx (no im2col).
// 93KB smem -> 2 CTAs/SM.
// ---------------------------------------------------------------------------
#define A_RS     144
#define A_PLANE  (130 * A_RS)          // 18720
#define A_TOTAL  (3 * A_PLANE)         // 56160
#define B_HALF   (64 * A_RS)           // 9216
#define B_SLOT   (2 * B_HALF)          // 18432
#define B_OFF    A_TOTAL
#define BIAS_OFF (A_TOTAL + 2 * B_SLOT)  // 93024
#define SMEM_DYN (BIAS_OFF + 256)

__global__ __launch_bounds__(256, 2)
void conv_mma_kernel(const float* __restrict__ x, float* __restrict__ out)
{
    extern __shared__ unsigned char sm[];
    const uint32_t sb = smem_u32(sm);
    const int tid = threadIdx.x;
    const int w   = tid >> 5;
    const int l   = tid & 31;
    const int px0 = blockIdx.x * 128;
    const int y   = blockIdx.y;
    const int b   = blockIdx.z;

    float* bias_s = (float*)(sm + BIAS_OFF);
    if (tid < 64) bias_s[tid] = g_b[b * COUT_ + tid];

    // ---- B cp.async: tap t -> slot --------------------------------------
    auto issueB = [&](int t, int slot) {
        const char* src = (const char*)g_whl4 + (size_t)(b * 9 + t) * 16384;
        uint32_t dst0 = sb + B_OFF + slot * B_SLOT;
        #pragma unroll
        for (int i = 0; i < 4; i++) {
            int idx = tid + i * 256;
            int hh  = idx >> 9;
            int row = (idx >> 3) & 63;
            int ch  = idx & 7;
            uint32_t d = dst0 + hh * B_HALF + row * A_RS + ch * 16;
            const char* s = src + (((hh * 64 + row) * 8 + ch) << 4);
            asm volatile("cp.async.cg.shared.global [%0], [%1], 16;"
                         :: "r"(d), "l"(s));
        }
    };

    issueB(0, 0);
    asm volatile("cp.async.commit_group;" ::: "memory");

    // ---- stage A: 3 ky planes (hi only); rows 0..129 = px0-1..px0+128 ----
    const float* xb = x + ((size_t)(b * CIN_) << 16);
    for (int u = tid; u < 12480; u += 256) {
        int ky  = u / 4160;
        int rem = u - ky * 4160;
        int cp  = rem / 130;          // cin pair
        int pr  = rem - cp * 130;     // plane row (pixel)
        int gy  = y + ky - 1;
        int gx  = px0 - 1 + pr;
        float v0 = 0.f, v1 = 0.f;
        if ((unsigned)gy < 256u && (unsigned)gx < 256u) {
            const float* p = xb + ((size_t)(cp * 2) << 16) + (gy << 8) + gx;
            v0 = p[0];
            v1 = p[(size_t)1 << 16];
        }
        *(__half2*)(sm + ky * A_PLANE + pr * A_RS + cp * 4) =
            __halves2half2(__float2half_rn(v0), __float2half_rn(v1));
    }

    // per-lane ldmatrix offsets
    const uint32_t a_off  = (uint32_t)((l & 15) * A_RS + (l >> 4) * 16);
    const uint32_t b4_off = (uint32_t)((((l >> 4) & 1) * 8 + (l & 7)) * A_RS
                                       + ((l >> 3) & 1) * 16);

    float c[8][4];
    #pragma unroll
    for (int nt = 0; nt < 8; nt++)
        #pragma unroll
        for (int q = 0; q < 4; q++) c[nt][q] = 0.f;

    #pragma unroll 1
    for (int t = 0; t < 9; t++) {
        if (t < 8) issueB(t + 1, (t + 1) & 1);
        asm volatile("cp.async.commit_group;" ::: "memory");   // empty @ t=8
        asm volatile("cp.async.wait_group 1;" ::: "memory");
        __syncthreads();   // B(t) (and A staging at t=0) visible

        const int ky = t / 3, kx = t - ky * 3;
        const uint32_t ahi = sb + ky * A_PLANE + (w * 16 + kx) * A_RS + a_off;
        const uint32_t bhi = sb + B_OFF + (t & 1) * B_SLOT + b4_off;
        const uint32_t blo = bhi + B_HALF;

        #pragma unroll
        for (int kc = 0; kc < 4; kc++) {
            uint32_t ah[4];
            ldsm4(ah, ahi + kc * 32);
            #pragma unroll
            for (int np = 0; np < 4; np++) {   // n-tile pairs
                uint32_t bh[4], bl[4];
                ldsm4(bh, bhi + np * 16 * A_RS + kc * 32);
                ldsm4(bl, blo + np * 16 * A_RS + kc * 32);
                mma16816(c[2 * np + 0], ah, bh + 0);   // hi*w_hi
                mma16816(c[2 * np + 0], ah, bl + 0);   // hi*w_lo
                mma16816(c[2 * np + 1], ah, bh + 2);
                mma16816(c[2 * np + 1], ah, bl + 2);
            }
        }
        __syncthreads();   // slot reads done before re-fill
    }

    // ---- epilogue: C[m=px][n=cout] + bias -> out[b][n][y][px] ------------
    const int gg  = l >> 2, tig = l & 3;
    const int pxb = px0 + w * 16 + gg;
    float* ob = out + (((size_t)b * COUT_) << 16) + (y << 8);
    #pragma unroll
    for (int nt = 0; nt < 8; nt++) {
        int n0 = nt * 8 + tig * 2;
        float bi0 = bias_s[n0], bi1 = bias_s[n0 + 1];
        ob[((size_t)n0 << 16) + pxb]           = c[nt][0] + bi0;
        ob[((size_t)(n0 + 1) << 16) + pxb]     = c[nt][1] + bi1;
        ob[((size_t)n0 << 16) + pxb + 8]       = c[nt][2] + bi0;
        ob[((size_t)(n0 + 1) << 16) + pxb + 8] = c[nt][3] + bi1;
    }
}

// ---------------------------------------------------------------------------
extern "C" void kernel_launch(void* const* d_in, const int* in_sizes, int n_in,
                              void* d_out, int out_size)
{
    const float* x           = (const float*)d_in[0];
    const float* h           = (const float*)d_in[1];
    const float* index       = (const float*)d_in[2];
    const float* conv_weight = (const float*)d_in[3];
    const float* conv_bias   = (const float*)d_in[4];
    const float* W_wp        = (const float*)d_in[5];
    const float* b_wp        = (const float*)d_in[6];
    const float* W_wi        = (const float*)d_in[7];
    const float* b_wi        = (const float*)d_in[8];
    const float* W_we        = (const float*)d_in[9];
    const float* b_we        = (const float*)d_in[10];
    const float* W_bp        = (const float*)d_in[11];
    const float* b_bp        = (const float*)d_in[12];
    const float* W_bi        = (const float*)d_in[13];
    const float* b_bi        = (const float*)d_in[14];
    float* out = (float*)d_out;

    cudaFuncSetAttribute(conv_mma_kernel,
                         cudaFuncAttributeMaxDynamicSharedMemorySize, SMEM_DYN);

    dim3 g1(8, 8);
    embed_kernel<<<g1, 256>>>(h, index, conv_weight, conv_bias,
                              W_wp, b_wp, W_wi, b_wi, W_we, b_we,
                              W_bp, b_bp, W_bi, b_bi);

    dim3 g2(2, 256, B_);
    conv_mma_kernel<<<g2, 256, SMEM_DYN>>>(x, out);
}

// round 11
// speedup vs baseline: 3.2998x; 1.1430x over previous
#include <cuda_runtime.h>
#include <cuda_fp16.h>
#include <cstdint>
#include <cstddef>

#define B_    8
#define CIN_  64
#define COUT_ 64
#define MID_  64
#define NP_   4
#define NL_   5

// ---------------- scratch (no cudaMalloc allowed) --------------------------
// fp16 weight planes: [b][tap(9)][cout(64)][cin(64)]  (8KB per tap)
__device__ uint4 g_wh4[B_ * 9 * 64 * 8];        // 576 KB
__device__ float g_b[B_ * COUT_];

// ---------------------------------------------------------------------------
// Kernel 1: hypernetwork embed -> fp16 weight planes + bias.
// grid (8 cin-groups, 8 batches, 4 jt-tiles). W_we tile (144x64) in smem,
// pad 68 so dots run on float4 LDS.128. All float4-read arrays 16B aligned.
// ---------------------------------------------------------------------------
__global__ __launch_bounds__(256)
void embed_kernel(
    const float* __restrict__ h,   const float* __restrict__ index,
    const float* __restrict__ conv_weight, const float* __restrict__ conv_bias,
    const float* __restrict__ W_wp, const float* __restrict__ b_wp,
    const float* __restrict__ W_wi, const float* __restrict__ b_wi,
    const float* __restrict__ W_we, const float* __restrict__ b_we,
    const float* __restrict__ W_bp, const float* __restrict__ b_bp,
    const float* __restrict__ W_bi, const float* __restrict__ b_bi)
{
    const int g  = blockIdx.x;      // cin group: cins [g*8, g*8+8)
    const int b  = blockIdx.y;
    const int jt = blockIdx.z;      // W_we row tile: rows [jt*144, jt*144+144)
    const int tid = threadIdx.x;

    __shared__ __align__(16) float w1[8 * MID_];     // float4-read: keep 16B
    __shared__ __align__(16) float Wt[144 * 68];     // 68*4=272 (16B multiple)
    __shared__ __align__(16) float hs[NP_];
    __shared__ __align__(16) float is_[NL_];

    if (tid < NP_) hs[tid] = h[b * NP_ + tid];
    if (tid < NL_) is_[tid] = index[tid];
    __syncthreads();

    for (int il = tid; il < 8 * MID_; il += 256) {
        int i = g * 8 * MID_ + il;
        float v = b_wp[i] + b_wi[i];
        #pragma unroll
        for (int p = 0; p < NP_; p++) v += hs[p] * W_wp[i * NP_ + p];
        #pragma unroll
        for (int l = 0; l < NL_; l++) v += is_[l] * W_wi[i * NL_ + l];
        w1[il] = v;
    }
    // coalesced tile load: rows jt*144 .. +143 of W_we[576][64]
    for (int idx = tid; idx < 144 * 64; idx += 256) {
        int r = idx >> 6, m = idx & 63;
        Wt[r * 68 + m] = W_we[(jt * 144 + r) * 64 + m];
    }
    __syncthreads();

    unsigned short* gw = (unsigned short*)g_wh4;

    for (int e = tid; e < 8 * 144; e += 256) {
        int cl  = e / 144;
        int jjl = e - cl * 144;
        int jj  = jt * 144 + jjl;                 // cout*9 + kk
        int cin = g * 8 + cl;
        float s = b_we[jj];
        const float4* wr  = (const float4*)&Wt[jjl * 68];
        const float4* w1r = (const float4*)&w1[cl * MID_];
        #pragma unroll
        for (int m = 0; m < 16; m++) {
            float4 a = w1r[m], q = wr[m];
            s += a.x * q.x + a.y * q.y + a.z * q.z + a.w * q.w;
        }
        int cout = jj / 9;
        int kk   = jj - cout * 9;                 // ky*3 + kx
        float wv = conv_weight[(cout * CIN_ + cin) * 9 + kk] + s;
        gw[(((size_t)(b * 9 + kk) * 64) + cout) * 64 + cin] =
            __half_as_ushort(__float2half_rn(wv));
    }

    if (g == 0 && jt == 0 && tid < COUT_) {
        float v = conv_bias[tid] + b_bp[tid] + b_bi[tid];
        #pragma unroll
        for (int p = 0; p < NP_; p++) v += hs[p] * W_bp[tid * NP_ + p];
        #pragma unroll
        for (int l = 0; l < NL_; l++) v += is_[l] * W_bi[tid * NL_ + l];
        g_b[b * COUT_ + tid] = v;
    }
}

// ---------------------------------------------------------------------------
// mma.sync / ldmatrix helpers (base-target ISA)
// ---------------------------------------------------------------------------
__device__ __forceinline__ uint32_t smem_u32(const void* p) {
    uint32_t a;
    asm("{ .reg .u64 t; cvta.to.shared.u64 t, %1; cvt.u32.u64 %0, t; }"
        : "=r"(a) : "l"(p));
    return a;
}
__device__ __forceinline__ void mma16816(float* c, const uint32_t* a,
                                         const uint32_t* b) {
    asm volatile(
        "mma.sync.aligned.m16n8k16.row.col.f32.f16.f16.f32 "
        "{%0,%1,%2,%3}, {%4,%5,%6,%7}, {%8,%9}, {%0,%1,%2,%3};"
        : "+f"(c[0]), "+f"(c[1]), "+f"(c[2]), "+f"(c[3])
        : "r"(a[0]), "r"(a[1]), "r"(a[2]), "r"(a[3]), "r"(b[0]), "r"(b[1]));
}
__device__ __forceinline__ void ldsm4(uint32_t* r, uint32_t addr) {
    asm volatile("ldmatrix.sync.aligned.m8n8.x4.shared.b16 {%0,%1,%2,%3}, [%4];"
        : "=r"(r[0]), "=r"(r[1]), "=r"(r[2]), "=r"(r[3]) : "r"(addr));
}

// ---------------------------------------------------------------------------
// Kernel 2: mma.sync conv. grid=(2,256,8) = (half-row, image row y, batch b).
// A: fp16 planes [ky 3][row 130][144B] (row=px, 64 fp16 cin + pad).
// B: fp16 (no split), 2-slot cp.async ring, per tap [cout 64][144B].
// Tap (ky,kx): A fragment rows shifted by kx (no im2col).
// ~75KB smem, <=84 regs -> 3 CTAs/SM.
// ---------------------------------------------------------------------------
#define A_RS     144
#define A_PLANE  (130 * A_RS)          // 18720
#define A_TOTAL  (3 * A_PLANE)         // 56160
#define B_SLOT   (64 * A_RS)           // 9216
#define B_OFF    A_TOTAL
#define BIAS_OFF (A_TOTAL + 2 * B_SLOT)  // 74592
#define SMEM_DYN (BIAS_OFF + 256)

__global__ __launch_bounds__(256, 3)
void conv_mma_kernel(const float* __restrict__ x, float* __restrict__ out)
{
    extern __shared__ __align__(16) unsigned char sm[];
    const uint32_t sb = smem_u32(sm);
    const int tid = threadIdx.x;
    const int w   = tid >> 5;
    const int l   = tid & 31;
    const int px0 = blockIdx.x * 128;
    const int y   = blockIdx.y;
    const int b   = blockIdx.z;

    float* bias_s = (float*)(sm + BIAS_OFF);
    if (tid < 64) bias_s[tid] = g_b[b * COUT_ + tid];

    // ---- B cp.async: tap t -> slot (8KB) ---------------------------------
    auto issueB = [&](int t, int slot) {
        const char* src = (const char*)g_wh4 + (size_t)(b * 9 + t) * 8192;
        uint32_t dst0 = sb + B_OFF + slot * B_SLOT;
        #pragma unroll
        for (int i = 0; i < 2; i++) {
            int idx = tid + i * 256;      // 0..511
            int row = idx >> 3;
            int ch  = idx & 7;
            uint32_t d = dst0 + row * A_RS + ch * 16;
            const char* s = src + ((size_t)idx << 4);
            asm volatile("cp.async.cg.shared.global [%0], [%1], 16;"
                         :: "r"(d), "l"(s));
        }
    };

    issueB(0, 0);
    asm volatile("cp.async.commit_group;" ::: "memory");

    // ---- stage A: 3 ky planes; rows 0..129 = px0-1 .. px0+128 ------------
    const float* xb = x + ((size_t)(b * CIN_) << 16);
    for (int u = tid; u < 12480; u += 256) {
        int ky  = u / 4160;
        int rem = u - ky * 4160;
        int cp  = rem / 130;          // cin pair
        int pr  = rem - cp * 130;     // plane row (pixel)
        int gy  = y + ky - 1;
        int gx  = px0 - 1 + pr;
        float v0 = 0.f, v1 = 0.f;
        if ((unsigned)gy < 256u && (unsigned)gx < 256u) {
            const float* p = xb + ((size_t)(cp * 2) << 16) + (gy << 8) + gx;
            v0 = p[0];
            v1 = p[(size_t)1 << 16];
        }
        *(__half2*)(sm + ky * A_PLANE + pr * A_RS + cp * 4) =
            __halves2half2(__float2half_rn(v0), __float2half_rn(v1));
    }

    // per-lane ldmatrix offsets
    const uint32_t a_off  = (uint32_t)((l & 15) * A_RS + (l >> 4) * 16);
    const uint32_t b4_off = (uint32_t)((((l >> 4) & 1) * 8 + (l & 7)) * A_RS
                                       + ((l >> 3) & 1) * 16);

    float c[8][4];
    #pragma unroll
    for (int nt = 0; nt < 8; nt++)
        #pragma unroll
        for (int q = 0; q < 4; q++) c[nt][q] = 0.f;

    #pragma unroll 1
    for (int t = 0; t < 9; t++) {
        if (t < 8) issueB(t + 1, (t + 1) & 1);
        asm volatile("cp.async.commit_group;" ::: "memory");   // empty @ t=8
        asm volatile("cp.async.wait_group 1;" ::: "memory");
        __syncthreads();   // B(t) (and A staging at t=0) visible

        const int ky = t / 3, kx = t - ky * 3;
        const uint32_t ahi = sb + ky * A_PLANE + (w * 16 + kx) * A_RS + a_off;
        const uint32_t bhi = sb + B_OFF + (t & 1) * B_SLOT + b4_off;

        uint32_t ah[4][4];
        #pragma unroll
        for (int kc = 0; kc < 4; kc++) ldsm4(ah[kc], ahi + kc * 32);

        #pragma unroll
        for (int np = 0; np < 4; np++) {      // n-tile pairs
            #pragma unroll
            for (int kc = 0; kc < 4; kc++) {
                uint32_t bh[4];
                ldsm4(bh, bhi + np * 16 * A_RS + kc * 32);
                mma16816(c[2 * np + 0], ah[kc], bh + 0);
                mma16816(c[2 * np + 1], ah[kc], bh + 2);
            }
        }
        __syncthreads();   // slot reads done before re-fill
    }

    // ---- epilogue: C[m=px][n=cout] + bias -> out[b][n][y][px] ------------
    const int gg  = l >> 2, tig = l & 3;
    const int pxb = px0 + w * 16 + gg;
    float* ob = out + (((size_t)b * COUT_) << 16) + (y << 8);
    #pragma unroll
    for (int nt = 0; nt < 8; nt++) {
        int n0 = nt * 8 + tig * 2;
        float bi0 = bias_s[n0], bi1 = bias_s[n0 + 1];
        ob[((size_t)n0 << 16) + pxb]           = c[nt][0] + bi0;
        ob[((size_t)(n0 + 1) << 16) + pxb]     = c[nt][1] + bi1;
        ob[((size_t)n0 << 16) + pxb + 8]       = c[nt][2] + bi0;
        ob[((size_t)(n0 + 1) << 16) + pxb + 8] = c[nt][3] + bi1;
    }
}

// ---------------------------------------------------------------------------
extern "C" void kernel_launch(void* const* d_in, const int* in_sizes, int n_in,
                              void* d_out, int out_size)
{
    const float* x           = (const float*)d_in[0];
    const float* h           = (const float*)d_in[1];
    const float* index       = (const float*)d_in[2];
    const float* conv_weight = (const float*)d_in[3];
    const float* conv_bias   = (const float*)d_in[4];
    const float* W_wp        = (const float*)d_in[5];
    const float* b_wp        = (const float*)d_in[6];
    const float* W_wi        = (const float*)d_in[7];
    const float* b_wi        = (const float*)d_in[8];
    const float* W_we        = (const float*)d_in[9];
    const float* b_we        = (const float*)d_in[10];
    const float* W_bp        = (const float*)d_in[11];
    const float* b_bp        = (const float*)d_in[12];
    const float* W_bi        = (const float*)d_in[13];
    const float* b_bi        = (const float*)d_in[14];
    float* out = (float*)d_out;

    cudaFuncSetAttribute(conv_mma_kernel,
                         cudaFuncAttributeMaxDynamicSharedMemorySize, SMEM_DYN);

    dim3 g1(8, 8, 4);
    embed_kernel<<<g1, 256>>>(h, index, conv_weight, conv_bias,
                              W_wp, b_wp, W_wi, b_wi, W_we, b_we,
                              W_bp, b_bp, W_bi, b_bi);

    dim3 g2(2, 256, B_);
    conv_mma_kernel<<<g2, 256, SMEM_DYN>>>(x, out);
}

// round 12
// speedup vs baseline: 6.4561x; 1.9565x over previous
#include <cuda_runtime.h>
#include <cuda_fp16.h>
#include <cstdint>
#include <cstddef>

#define B_    8
#define CIN_  64
#define COUT_ 64
#define MID_  64
#define NP_   4
#define NL_   5

// ---------------- scratch (no cudaMalloc allowed) --------------------------
// fp16 weight planes: [b][tap(9)][cout(64)][cin(64)]  (8KB per tap)
__device__ uint4 g_wh4[B_ * 9 * 64 * 8];        // 576 KB
__device__ float g_b[B_ * COUT_];

// ---------------------------------------------------------------------------
// Kernel 1: hypernetwork embed -> fp16 weight planes + bias.
// ---------------------------------------------------------------------------
__global__ __launch_bounds__(256)
void embed_kernel(
    const float* __restrict__ h,   const float* __restrict__ index,
    const float* __restrict__ conv_weight, const float* __restrict__ conv_bias,
    const float* __restrict__ W_wp, const float* __restrict__ b_wp,
    const float* __restrict__ W_wi, const float* __restrict__ b_wi,
    const float* __restrict__ W_we, const float* __restrict__ b_we,
    const float* __restrict__ W_bp, const float* __restrict__ b_bp,
    const float* __restrict__ W_bi, const float* __restrict__ b_bi)
{
    const int g  = blockIdx.x;      // cin group: cins [g*8, g*8+8)
    const int b  = blockIdx.y;
    const int jt = blockIdx.z;      // W_we row tile: rows [jt*144, jt*144+144)
    const int tid = threadIdx.x;

    __shared__ __align__(16) float w1[8 * MID_];
    __shared__ __align__(16) float Wt[144 * 68];
    __shared__ __align__(16) float hs[NP_];
    __shared__ __align__(16) float is_[NL_];

    if (tid < NP_) hs[tid] = h[b * NP_ + tid];
    if (tid < NL_) is_[tid] = index[tid];
    __syncthreads();

    for (int il = tid; il < 8 * MID_; il += 256) {
        int i = g * 8 * MID_ + il;
        float v = b_wp[i] + b_wi[i];
        #pragma unroll
        for (int p = 0; p < NP_; p++) v += hs[p] * W_wp[i * NP_ + p];
        #pragma unroll
        for (int l = 0; l < NL_; l++) v += is_[l] * W_wi[i * NL_ + l];
        w1[il] = v;
    }
    for (int idx = tid; idx < 144 * 64; idx += 256) {
        int r = idx >> 6, m = idx & 63;
        Wt[r * 68 + m] = W_we[(jt * 144 + r) * 64 + m];
    }
    __syncthreads();

    unsigned short* gw = (unsigned short*)g_wh4;

    for (int e = tid; e < 8 * 144; e += 256) {
        int cl  = e / 144;
        int jjl = e - cl * 144;
        int jj  = jt * 144 + jjl;                 // cout*9 + kk
        int cin = g * 8 + cl;
        float s = b_we[jj];
        const float4* wr  = (const float4*)&Wt[jjl * 68];
        const float4* w1r = (const float4*)&w1[cl * MID_];
        #pragma unroll
        for (int m = 0; m < 16; m++) {
            float4 a = w1r[m], q = wr[m];
            s += a.x * q.x + a.y * q.y + a.z * q.z + a.w * q.w;
        }
        int cout = jj / 9;
        int kk   = jj - cout * 9;                 // ky*3 + kx
        float wv = conv_weight[(cout * CIN_ + cin) * 9 + kk] + s;
        gw[(((size_t)(b * 9 + kk) * 64) + cout) * 64 + cin] =
            __half_as_ushort(__float2half_rn(wv));
    }

    if (g == 0 && jt == 0 && tid < COUT_) {
        float v = conv_bias[tid] + b_bp[tid] + b_bi[tid];
        #pragma unroll
        for (int p = 0; p < NP_; p++) v += hs[p] * W_bp[tid * NP_ + p];
        #pragma unroll
        for (int l = 0; l < NL_; l++) v += is_[l] * W_bi[tid * NL_ + l];
        g_b[b * COUT_ + tid] = v;
    }
}

// ---------------------------------------------------------------------------
// mma.sync / ldmatrix helpers
// ---------------------------------------------------------------------------
__device__ __forceinline__ uint32_t smem_u32(const void* p) {
    uint32_t a;
    asm("{ .reg .u64 t; cvta.to.shared.u64 t, %1; cvt.u32.u64 %0, t; }"
        : "=r"(a) : "l"(p));
    return a;
}
__device__ __forceinline__ void mma16816(float* c, const uint32_t* a,
                                         const uint32_t* b) {
    asm volatile(
        "mma.sync.aligned.m16n8k16.row.col.f32.f16.f16.f32 "
        "{%0,%1,%2,%3}, {%4,%5,%6,%7}, {%8,%9}, {%0,%1,%2,%3};"
        : "+f"(c[0]), "+f"(c[1]), "+f"(c[2]), "+f"(c[3])
        : "r"(a[0]), "r"(a[1]), "r"(a[2]), "r"(a[3]), "r"(b[0]), "r"(b[1]));
}
__device__ __forceinline__ void ldsm4(uint32_t* r, uint32_t addr) {
    asm volatile("ldmatrix.sync.aligned.m8n8.x4.shared.b16 {%0,%1,%2,%3}, [%4];"
        : "=r"(r[0]), "=r"(r[1]), "=r"(r[2]), "=r"(r[3]) : "r"(addr));
}

// ---------------------------------------------------------------------------
// Kernel 2: mma.sync conv. grid=(2,128,8) = (x-half, y-row-pair, batch).
// CTA covers 2 output rows x 128 px x 64 couts. 8 warps: warp w -> output
// row (w>>2), px quarter (w&3)*32 ; per-warp M=32 (two m16 tiles), N=64.
// A: fp16 planes [4 input rows][130 px-rows][144B]; tap (ky,kx) = plane
// (wrow+ky), px rows shifted by kx. B: 2-slot cp.async ring per tap.
// ---------------------------------------------------------------------------
#define A_RS     144
#define A_PLANE  (130 * A_RS)          // 18720
#define A_TOTAL  (4 * A_PLANE)         // 74880
#define B_SLOT   (64 * A_RS)           // 9216
#define B_OFF    A_TOTAL
#define BIAS_OFF (A_TOTAL + 2 * B_SLOT)  // 93312
#define SMEM_DYN (BIAS_OFF + 256)

__global__ __launch_bounds__(256, 2)
void conv_mma_kernel(const float* __restrict__ x, float* __restrict__ out)
{
    extern __shared__ __align__(16) unsigned char sm[];
    const uint32_t sb = smem_u32(sm);
    const int tid = threadIdx.x;
    const int w   = tid >> 5;
    const int l   = tid & 31;
    const int px0 = blockIdx.x * 128;
    const int y0  = blockIdx.y * 2;
    const int b   = blockIdx.z;

    float* bias_s = (float*)(sm + BIAS_OFF);
    if (tid < 64) bias_s[tid] = g_b[b * COUT_ + tid];

    // ---- B cp.async: tap t -> slot (8KB) ---------------------------------
    auto issueB = [&](int t, int slot) {
        const char* src = (const char*)g_wh4 + (size_t)(b * 9 + t) * 8192;
        uint32_t dst0 = sb + B_OFF + slot * B_SLOT;
        #pragma unroll
        for (int i = 0; i < 2; i++) {
            int idx = tid + i * 256;      // 0..511
            int row = idx >> 3;
            int ch  = idx & 7;
            uint32_t d = dst0 + row * A_RS + ch * 16;
            const char* s = src + ((size_t)idx << 4);
            asm volatile("cp.async.cg.shared.global [%0], [%1], 16;"
                         :: "r"(d), "l"(s));
        }
    };

    issueB(0, 0);
    asm volatile("cp.async.commit_group;" ::: "memory");

    // ---- stage A: 4 input-row planes; plane rows 0..129 = px0-1..px0+128 -
    const float* xb = x + ((size_t)(b * CIN_) << 16);
    // main: plane rows 1..128 via float2 (2 px per item)
    for (int u = tid; u < 8192; u += 256) {
        int ky  = u >> 11;                 // input row = y0-1+ky
        int rem = u & 2047;
        int cp  = rem >> 6;                // cin pair
        int p2  = rem & 63;                // px pair: rows 1+2p2, 2+2p2
        int gy  = y0 - 1 + ky;
        int gx  = px0 + 2 * p2;            // even -> aligned float2
        float2 v0 = make_float2(0.f, 0.f), v1 = make_float2(0.f, 0.f);
        if ((unsigned)gy < 256u) {
            const float* p = xb + ((size_t)(cp * 2) << 16) + (gy << 8) + gx;
            v0 = *(const float2*)p;
            v1 = *(const float2*)(p + ((size_t)1 << 16));
        }
        unsigned char* pl = sm + ky * A_PLANE + cp * 4;
        *(__half2*)(pl + (1 + 2 * p2) * A_RS) =
            __halves2half2(__float2half_rn(v0.x), __float2half_rn(v1.x));
        *(__half2*)(pl + (2 + 2 * p2) * A_RS) =
            __halves2half2(__float2half_rn(v0.y), __float2half_rn(v1.y));
    }
    // edges: plane rows 0 (px0-1) and 129 (px0+128)
    for (int u = tid; u < 256; u += 256) {
        int ky   = u >> 6;
        int rem  = u & 63;
        int side = rem >> 5;
        int cp   = rem & 31;
        int gy   = y0 - 1 + ky;
        int gx   = side ? (px0 + 128) : (px0 - 1);
        int r    = side ? 129 : 0;
        float a0 = 0.f, a1 = 0.f;
        if ((unsigned)gy < 256u && (unsigned)gx < 256u) {
            const float* p = xb + ((size_t)(cp * 2) << 16) + (gy << 8) + gx;
            a0 = p[0];
            a1 = p[(size_t)1 << 16];
        }
        *(__half2*)(sm + ky * A_PLANE + r * A_RS + cp * 4) =
            __halves2half2(__float2half_rn(a0), __float2half_rn(a1));
    }

    // per-lane ldmatrix offsets
    const uint32_t a_off  = (uint32_t)((l & 15) * A_RS + (l >> 4) * 16);
    const uint32_t b4_off = (uint32_t)((((l >> 4) & 1) * 8 + (l & 7)) * A_RS
                                       + ((l >> 3) & 1) * 16);

    const int wrow = w >> 2;          // output row within pair
    const int wpx  = (w & 3) * 32;    // px quarter

    float c[2][8][4];                 // [m-tile][n-tile][frag]
    #pragma unroll
    for (int mt = 0; mt < 2; mt++)
        #pragma unroll
        for (int nt = 0; nt < 8; nt++)
            #pragma unroll
            for (int q = 0; q < 4; q++) c[mt][nt][q] = 0.f;

    #pragma unroll 1
    for (int t = 0; t < 9; t++) {
        if (t < 8) issueB(t + 1, (t + 1) & 1);
        asm volatile("cp.async.commit_group;" ::: "memory");   // empty @ t=8
        asm volatile("cp.async.wait_group 1;" ::: "memory");
        __syncthreads();   // B(t) (and A staging at t=0) visible

        const int ky = t / 3, kx = t - ky * 3;
        const uint32_t abase = sb + (wrow + ky) * A_PLANE
                             + (wpx + kx) * A_RS + a_off;
        const uint32_t bhi = sb + B_OFF + (t & 1) * B_SLOT + b4_off;

        #pragma unroll
        for (int kc = 0; kc < 4; kc++) {
            uint32_t a0[4], a1[4];
            ldsm4(a0, abase + kc * 32);
            ldsm4(a1, abase + 16 * A_RS + kc * 32);
            #pragma unroll
            for (int np = 0; np < 4; np++) {
                uint32_t bh[4];
                ldsm4(bh, bhi + np * 16 * A_RS + kc * 32);
                mma16816(c[0][2 * np + 0], a0, bh + 0);
                mma16816(c[0][2 * np + 1], a0, bh + 2);
                mma16816(c[1][2 * np + 0], a1, bh + 0);
                mma16816(c[1][2 * np + 1], a1, bh + 2);
            }
        }
        __syncthreads();   // slot reads done before re-fill
    }

    // ---- epilogue: C[m=px][n=cout] + bias -> out[b][n][y0+wrow][px] ------
    const int gg  = l >> 2, tig = l & 3;
    float* ob = out + (((size_t)b * COUT_) << 16) + ((y0 + wrow) << 8);
    #pragma unroll
    for (int mt = 0; mt < 2; mt++) {
        int pxb = px0 + wpx + mt * 16 + gg;
        #pragma unroll
        for (int nt = 0; nt < 8; nt++) {
            int n0 = nt * 8 + tig * 2;
            float bi0 = bias_s[n0], bi1 = bias_s[n0 + 1];
            ob[((size_t)n0 << 16) + pxb]           = c[mt][nt][0] + bi0;
            ob[((size_t)(n0 + 1) << 16) + pxb]     = c[mt][nt][1] + bi1;
            ob[((size_t)n0 << 16) + pxb + 8]       = c[mt][nt][2] + bi0;
            ob[((size_t)(n0 + 1) << 16) + pxb + 8] = c[mt][nt][3] + bi1;
        }
    }
}

// ---------------------------------------------------------------------------
extern "C" void kernel_launch(void* const* d_in, const int* in_sizes, int n_in,
                              void* d_out, int out_size)
{
    const float* x           = (const float*)d_in[0];
    const float* h           = (const float*)d_in[1];
    const float* index       = (const float*)d_in[2];
    const float* conv_weight = (const float*)d_in[3];
    const float* conv_bias   = (const float*)d_in[4];
    const float* W_wp        = (const float*)d_in[5];
    const float* b_wp        = (const float*)d_in[6];
    const float* W_wi        = (const float*)d_in[7];
    const float* b_wi        = (const float*)d_in[8];
    const float* W_we        = (const float*)d_in[9];
    const float* b_we        = (const float*)d_in[10];
    const float* W_bp        = (const float*)d_in[11];
    const float* b_bp        = (const float*)d_in[12];
    const float* W_bi        = (const float*)d_in[13];
    const float* b_bi        = (const float*)d_in[14];
    float* out = (float*)d_out;

    cudaFuncSetAttribute(conv_mma_kernel,
                         cudaFuncAttributeMaxDynamicSharedMemorySize, SMEM_DYN);

    dim3 g1(8, 8, 4);
    embed_kernel<<<g1, 256>>>(h, index, conv_weight, conv_bias,
                              W_wp, b_wp, W_wi, b_wi, W_we, b_we,
                              W_bp, b_bp, W_bi, b_bi);

    dim3 g2(2, 128, B_);
    conv_mma_kernel<<<g2, 256, SMEM_DYN>>>(x, out);
}